// round 1
// baseline (speedup 1.0000x reference)
#include <cuda_runtime.h>

typedef unsigned long long u64;

// ---------- f32x2 packed helpers (sm_100+) ----------
static __device__ __forceinline__ u64 pk2(float lo, float hi) {
    u64 r; asm("mov.b64 %0, {%1, %2};" : "=l"(r) : "f"(lo), "f"(hi)); return r;
}
static __device__ __forceinline__ void upk2(u64 v, float& lo, float& hi) {
    asm("mov.b64 {%0, %1}, %2;" : "=f"(lo), "=f"(hi) : "l"(v));
}
static __device__ __forceinline__ u64 ffma2(u64 a, u64 b, u64 c) {
    u64 d; asm("fma.rn.f32x2 %0, %1, %2, %3;" : "=l"(d) : "l"(a), "l"(b), "l"(c)); return d;
}
static __device__ __forceinline__ u64 fadd2(u64 a, u64 b) {
    u64 d; asm("add.rn.f32x2 %0, %1, %2;" : "=l"(d) : "l"(a), "l"(b)); return d;
}

static __device__ __forceinline__ float softplus_f(float x) {
    // stable: max(x,0) + log1p(exp(-|x|))
    return fmaxf(x, 0.0f) + log1pf(__expf(-fabsf(x)));
}

// leaky_relu(a) = 0.505*a + 0.495*|a|  (slope 0.01)
#define C_HALF_P 0.505f
#define C_HALF_M 0.495f

__global__ __launch_bounds__(256)
void dln_kernel(const float* __restrict__ x,
                const float* __restrict__ W1, const float* __restrict__ b1,
                const float* __restrict__ Wd, const float* __restrict__ bd,
                const float* __restrict__ Wo, const float* __restrict__ bo,
                float* __restrict__ out, int n, int npairs)
{
    // Duplicated-weight shared layouts so one LDS.128 returns TWO packed f32x2 operands.
    __shared__ ulonglong2 sW1[128];  // j in [0,64): sW1[2j+p] = (dup w[j][2p], dup w[j][2p+1])
    __shared__ ulonglong2 sB1[32];   // jp: (dup b1[2jp], dup b1[2jp+1])
    __shared__ ulonglong2 sV[96];    // m*32+jp: (dup 0.495*V_m[2jp], dup 0.495*V_m[2jp+1])
    __shared__ u64 sM[12];           // dup of 0.505*(V_m W1)[k], index m*4+k
    __shared__ u64 sC[3];            // dup of bias_m + 0.505*(V_m . b1)

    float* fW1 = reinterpret_cast<float*>(sW1);
    float* fB1 = reinterpret_cast<float*>(sB1);
    float* fV  = reinterpret_cast<float*>(sV);
    float* fM  = reinterpret_cast<float*>(sM);
    float* fC  = reinterpret_cast<float*>(sC);

    const int t = threadIdx.x;

    // ---- per-block weight prep (tiny: ~530 floats from L2) ----
    { // W1 dup fill: 256 entries, 256 threads
        int j = t >> 2, k = t & 3;
        float v = W1[t];
        int base = j * 8 + (k >> 1) * 4 + ((k & 1) << 1);
        fW1[base] = v; fW1[base + 1] = v;
    }
    if (t < 64) {
        float v = b1[t];
        int base = (t >> 1) * 4 + ((t & 1) << 1);
        fB1[base] = v; fB1[base + 1] = v;
    }
    if (t < 192) {
        int m = t >> 6, j = t & 63;
        float v = ((m < 2) ? Wd[m * 64 + j] : Wo[j]) * C_HALF_M;
        int base = m * 128 + (j >> 1) * 4 + ((j & 1) << 1);
        fV[base] = v; fV[base + 1] = v;
    }
    if (t < 12) { // M = 0.505 * (V W1), entry (m,k)
        int m = t >> 2, k = t & 3;
        const float* Vm = (m == 0) ? Wd : ((m == 1) ? (Wd + 64) : Wo);
        float s = 0.0f;
        #pragma unroll 8
        for (int j = 0; j < 64; ++j) s = fmaf(Vm[j], W1[j * 4 + k], s);
        float v = C_HALF_P * s;
        fM[t * 2] = v; fM[t * 2 + 1] = v;
    }
    if (t >= 12 && t < 15) { // c_m = bias_m + 0.505*(V_m . b1)
        int m = t - 12;
        const float* Vm = (m == 0) ? Wd : ((m == 1) ? (Wd + 64) : Wo);
        float s = 0.0f;
        #pragma unroll 8
        for (int j = 0; j < 64; ++j) s = fmaf(Vm[j], b1[j], s);
        float bias = (m == 0) ? bd[0] : ((m == 1) ? bd[1] : bo[0]);
        float v = bias + C_HALF_P * s;
        fC[m * 2] = v; fC[m * 2 + 1] = v;
    }
    __syncthreads();

    const int pair = blockIdx.x * 256 + t;
    if (pair >= npairs) return;

    const float4* x4 = reinterpret_cast<const float4*>(x);
    float4* o4 = reinterpret_cast<float4*>(out);

    const int rA = 2 * pair;
    const bool hasB = (rA + 1) < n;
    float4 xa = x4[rA];
    float4 xb = hasB ? x4[rA + 1] : make_float4(0.f, 0.f, 0.f, 0.f);

    // pack: lo = row A, hi = row B
    u64 X0 = pk2(xa.x, xb.x);
    u64 X1 = pk2(xa.y, xb.y);
    u64 X2 = pk2(xa.z, xb.z);
    u64 X3 = pk2(xa.w, xb.w);

    u64 S0 = 0ull, S1 = 0ull, S2 = 0ull; // packed (0.0, 0.0)
    const u64 ABSM = 0x7fffffff7fffffffULL;

    #pragma unroll
    for (int jp = 0; jp < 32; ++jp) {
        ulonglong2 bb = sB1[jp];
        ulonglong2 w0 = sW1[4 * jp + 0];
        ulonglong2 w1 = sW1[4 * jp + 1];
        ulonglong2 w2 = sW1[4 * jp + 2];
        ulonglong2 w3 = sW1[4 * jp + 3];

        u64 a0 = bb.x; // j = 2*jp
        a0 = ffma2(w0.x, X0, a0);
        a0 = ffma2(w0.y, X1, a0);
        a0 = ffma2(w1.x, X2, a0);
        a0 = ffma2(w1.y, X3, a0);

        u64 a1 = bb.y; // j = 2*jp+1
        a1 = ffma2(w2.x, X0, a1);
        a1 = ffma2(w2.y, X1, a1);
        a1 = ffma2(w3.x, X2, a1);
        a1 = ffma2(w3.y, X3, a1);

        a0 &= ABSM;  // packed |a|
        a1 &= ABSM;

        ulonglong2 v0 = sV[jp];
        ulonglong2 v1 = sV[32 + jp];
        ulonglong2 v2 = sV[64 + jp];
        S0 = ffma2(v0.x, a0, S0); S0 = ffma2(v0.y, a1, S0);
        S1 = ffma2(v1.x, a0, S1); S1 = ffma2(v1.y, a1, S1);
        S2 = ffma2(v2.x, a0, S2); S2 = ffma2(v2.y, a1, S2);
    }

    // z_m = c_m + M_m . x + S_m   (all packed over 2 rows)
    u64 z0 = sC[0], z1 = sC[1], z2 = sC[2];
    z0 = ffma2(sM[0], X0, z0); z0 = ffma2(sM[1], X1, z0);
    z0 = ffma2(sM[2], X2, z0); z0 = ffma2(sM[3], X3, z0);
    z1 = ffma2(sM[4], X0, z1); z1 = ffma2(sM[5], X1, z1);
    z1 = ffma2(sM[6], X2, z1); z1 = ffma2(sM[7], X3, z1);
    z2 = ffma2(sM[8], X0, z2); z2 = ffma2(sM[9], X1, z2);
    z2 = ffma2(sM[10], X2, z2); z2 = ffma2(sM[11], X3, z2);
    z0 = fadd2(z0, S0);
    z1 = fadd2(z1, S1);
    z2 = fadd2(z2, S2);

    float z0a, z0b, z1a, z1b, z2a, z2b;
    upk2(z0, z0a, z0b);
    upk2(z1, z1a, z1b);
    upk2(z2, z2a, z2b);

    // Row A epilogue: L = [[d0,0],[lo,d1]], H = L L^T + 1e-9 I
    {
        float d0 = softplus_f(z0a);
        float d1 = softplus_f(z1a);
        float lo = z2a;
        float4 o;
        o.x = fmaf(d0, d0, 1e-9f);
        o.y = d0 * lo;
        o.z = o.y;
        o.w = fmaf(lo, lo, fmaf(d1, d1, 1e-9f));
        o4[rA] = o;
    }
    if (hasB) {
        float d0 = softplus_f(z0b);
        float d1 = softplus_f(z1b);
        float lo = z2b;
        float4 o;
        o.x = fmaf(d0, d0, 1e-9f);
        o.y = d0 * lo;
        o.z = o.y;
        o.w = fmaf(lo, lo, fmaf(d1, d1, 1e-9f));
        o4[rA + 1] = o;
    }
}

extern "C" void kernel_launch(void* const* d_in, const int* in_sizes, int n_in,
                              void* d_out, int out_size)
{
    const float* x  = (const float*)d_in[0];
    const float* W1 = (const float*)d_in[1];
    const float* b1 = (const float*)d_in[2];
    const float* Wd = (const float*)d_in[3];
    const float* bd = (const float*)d_in[4];
    const float* Wo = (const float*)d_in[5];
    const float* bo = (const float*)d_in[6];
    float* out = (float*)d_out;

    int n = in_sizes[0] / 4;            // rows
    int npairs = (n + 1) / 2;           // 2 rows per thread (f32x2 packed)
    int blocks = (npairs + 255) / 256;

    dln_kernel<<<blocks, 256>>>(x, W1, b1, Wd, bd, Wo, bo, out, n, npairs);
}

// round 2
// speedup vs baseline: 1.6702x; 1.6702x over previous
#include <cuda_runtime.h>

typedef unsigned long long u64;

// ---------- f32x2 packed helpers (sm_100+) ----------
static __device__ __forceinline__ u64 pk2(float lo, float hi) {
    u64 r; asm("mov.b64 %0, {%1, %2};" : "=l"(r) : "f"(lo), "f"(hi)); return r;
}
static __device__ __forceinline__ void upk2(u64 v, float& lo, float& hi) {
    asm("mov.b64 {%0, %1}, %2;" : "=f"(lo), "=f"(hi) : "l"(v));
}
static __device__ __forceinline__ u64 ffma2(u64 a, u64 b, u64 c) {
    u64 d; asm("fma.rn.f32x2 %0, %1, %2, %3;" : "=l"(d) : "l"(a), "l"(b), "l"(c)); return d;
}

static __device__ __forceinline__ float softplus_fast(float v) {
    // max(v,0) + log(1 + exp(-|v|)); |z| stays O(few), so __logf/__expf
    // error ~1e-6 rel — far below the 1e-3 gate.
    return fmaxf(v, 0.0f) + __logf(1.0f + __expf(-fabsf(v)));
}

#define C_HALF_P 0.505f
#define C_HALF_M 0.495f
#define ROWS_PER_THREAD 4
#define TPB 256
#define ROWS_PER_BLOCK (TPB * ROWS_PER_THREAD)

__global__ __launch_bounds__(TPB)
void dln_kernel(const float* __restrict__ x,
                const float* __restrict__ W1, const float* __restrict__ b1,
                const float* __restrict__ Wd, const float* __restrict__ bd,
                const float* __restrict__ Wo, const float* __restrict__ bo,
                float* __restrict__ out, int n)
{
    // Per j-pair jp (32 of them), 8 u64 = 64B:
    //  [0..3]: k=0..3 -> (W1[2jp][k], W1[2jp+1][k])       (natural j-pair pack)
    //  [4]   : (b1[2jp], b1[2jp+1])
    //  [5..7]: m=0..2 -> 0.495*(V_m[2jp], V_m[2jp+1])
    __shared__ ulonglong2 sw[128];   // sw[jp*4 + 0..3]
    __shared__ float sM[12];         // 0.505*(V_m W1)[k]   (m*4+k)
    __shared__ float sC[3];          // bias_m + 0.505*(V_m . b1)

    float* fS = reinterpret_cast<float*>(sw);
    const int t = threadIdx.x;

    // ---- weight prep (tiny) ----
    {
        int e = t;              // 256 u64 entries, one per thread
        int jp = e >> 3, q = e & 7;
        int j0 = 2 * jp, j1 = j0 + 1;
        float lo, hi;
        if (q < 4) {
            lo = W1[j0 * 4 + q]; hi = W1[j1 * 4 + q];
        } else if (q == 4) {
            lo = b1[j0]; hi = b1[j1];
        } else {
            int m = q - 5;
            const float* Vm = (m < 2) ? (Wd + m * 64) : Wo;
            lo = C_HALF_M * Vm[j0]; hi = C_HALF_M * Vm[j1];
        }
        fS[2 * e] = lo; fS[2 * e + 1] = hi;
    }
    if (t < 12) { // M = 0.505 * (V W1)
        int m = t >> 2, k = t & 3;
        const float* Vm = (m == 0) ? Wd : ((m == 1) ? (Wd + 64) : Wo);
        float s = 0.0f;
        #pragma unroll 8
        for (int j = 0; j < 64; ++j) s = fmaf(Vm[j], W1[j * 4 + k], s);
        sM[t] = C_HALF_P * s;
    }
    if (t >= 12 && t < 15) { // c_m = bias_m + 0.505*(V_m . b1)
        int m = t - 12;
        const float* Vm = (m == 0) ? Wd : ((m == 1) ? (Wd + 64) : Wo);
        float s = 0.0f;
        #pragma unroll 8
        for (int j = 0; j < 64; ++j) s = fmaf(Vm[j], b1[j], s);
        float bias = (m == 0) ? bd[0] : ((m == 1) ? bd[1] : bo[0]);
        sC[m] = bias + C_HALF_P * s;
    }
    __syncthreads();

    const int rowBase = blockIdx.x * ROWS_PER_BLOCK + t;   // coalesced: +i*TPB
    const float4* x4 = reinterpret_cast<const float4*>(x);
    float4* o4 = reinterpret_cast<float4*>(out);
    const u64 ABSM = 0x7fffffff7fffffffULL;

    // ---- load x for 4 rows, build dup-packed X ----
    u64 X[ROWS_PER_THREAD][4];
    bool ok[ROWS_PER_THREAD];
    float4 xi[ROWS_PER_THREAD];
    #pragma unroll
    for (int i = 0; i < ROWS_PER_THREAD; ++i) {
        int r = rowBase + i * TPB;
        ok[i] = (r < n);
        xi[i] = ok[i] ? x4[r] : make_float4(0.f, 0.f, 0.f, 0.f);
        X[i][0] = pk2(xi[i].x, xi[i].x);
        X[i][1] = pk2(xi[i].y, xi[i].y);
        X[i][2] = pk2(xi[i].z, xi[i].z);
        X[i][3] = pk2(xi[i].w, xi[i].w);
    }

    u64 S0[ROWS_PER_THREAD], S1[ROWS_PER_THREAD], S2[ROWS_PER_THREAD];
    #pragma unroll
    for (int i = 0; i < ROWS_PER_THREAD; ++i) { S0[i] = 0ull; S1[i] = 0ull; S2[i] = 0ull; }

    #pragma unroll
    for (int jp = 0; jp < 32; ++jp) {
        ulonglong2 e01 = sw[jp * 4 + 0];  // w k0, k1
        ulonglong2 e23 = sw[jp * 4 + 1];  // w k2, k3
        ulonglong2 e45 = sw[jp * 4 + 2];  // bias, v0
        ulonglong2 e67 = sw[jp * 4 + 3];  // v1, v2

        #pragma unroll
        for (int i = 0; i < ROWS_PER_THREAD; ++i) {
            u64 a = e45.x;                       // (b1[2jp], b1[2jp+1])
            a = ffma2(e01.x, X[i][0], a);
            a = ffma2(e01.y, X[i][1], a);
            a = ffma2(e23.x, X[i][2], a);
            a = ffma2(e23.y, X[i][3], a);
            a &= ABSM;                           // packed |a|
            S0[i] = ffma2(e45.y, a, S0[i]);
            S1[i] = ffma2(e67.x, a, S1[i]);
            S2[i] = ffma2(e67.y, a, S2[i]);
        }
    }

    const float m0 = sM[0], m1 = sM[1], m2 = sM[2],  m3 = sM[3];
    const float m4 = sM[4], m5 = sM[5], m6 = sM[6],  m7 = sM[7];
    const float m8 = sM[8], m9 = sM[9], m10 = sM[10], m11 = sM[11];
    const float c0 = sC[0], c1 = sC[1], c2 = sC[2];

    #pragma unroll
    for (int i = 0; i < ROWS_PER_THREAD; ++i) {
        if (!ok[i]) continue;
        float lo_, hi_;
        upk2(S0[i], lo_, hi_); float s0 = lo_ + hi_;
        upk2(S1[i], lo_, hi_); float s1 = lo_ + hi_;
        upk2(S2[i], lo_, hi_); float s2 = lo_ + hi_;
        float4 xv = xi[i];
        float z0 = fmaf(m3,  xv.w, fmaf(m2,  xv.z, fmaf(m1, xv.y, fmaf(m0, xv.x, c0)))) + s0;
        float z1 = fmaf(m7,  xv.w, fmaf(m6,  xv.z, fmaf(m5, xv.y, fmaf(m4, xv.x, c1)))) + s1;
        float z2 = fmaf(m11, xv.w, fmaf(m10, xv.z, fmaf(m9, xv.y, fmaf(m8, xv.x, c2)))) + s2;

        float d0 = softplus_fast(z0);
        float d1 = softplus_fast(z1);
        float l  = z2;
        float4 o;
        o.x = fmaf(d0, d0, 1e-9f);
        o.y = d0 * l;
        o.z = o.y;
        o.w = fmaf(l, l, fmaf(d1, d1, 1e-9f));
        o4[rowBase + i * TPB] = o;
    }
}

extern "C" void kernel_launch(void* const* d_in, const int* in_sizes, int n_in,
                              void* d_out, int out_size)
{
    const float* x  = (const float*)d_in[0];
    const float* W1 = (const float*)d_in[1];
    const float* b1 = (const float*)d_in[2];
    const float* Wd = (const float*)d_in[3];
    const float* bd = (const float*)d_in[4];
    const float* Wo = (const float*)d_in[5];
    const float* bo = (const float*)d_in[6];
    float* out = (float*)d_out;

    int n = in_sizes[0] / 4;                       // rows
    int blocks = (n + ROWS_PER_BLOCK - 1) / ROWS_PER_BLOCK;

    dln_kernel<<<blocks, TPB>>>(x, W1, b1, Wd, bd, Wo, bo, out, n);
}

// round 4
// speedup vs baseline: 1.6796x; 1.0056x over previous
#include <cuda_runtime.h>

typedef unsigned long long u64;

// ---------- f32x2 packed helpers (sm_100+) ----------
static __device__ __forceinline__ u64 pk2(float lo, float hi) {
    u64 r; asm("mov.b64 %0, {%1, %2};" : "=l"(r) : "f"(lo), "f"(hi)); return r;
}
static __device__ __forceinline__ void upk2(u64 v, float& lo, float& hi) {
    asm("mov.b64 {%0, %1}, %2;" : "=f"(lo), "=f"(hi) : "l"(v));
}
static __device__ __forceinline__ u64 ffma2(u64 a, u64 b, u64 c) {
    u64 d; asm("fma.rn.f32x2 %0, %1, %2, %3;" : "=l"(d) : "l"(a), "l"(b), "l"(c)); return d;
}

static __device__ __forceinline__ float softplus_fast(float v) {
    // max(v,0) + log(1 + exp(-|v|)); |z| is O(few) so fast-math err ~1e-6.
    return fmaxf(v, 0.0f) + __logf(1.0f + __expf(-fabsf(v)));
}

#define C_HALF_P 0.505f
#define C_HALF_M 0.495f
#define ROWS_PER_THREAD 4
#define TPB 256
#define ROWS_PER_BLOCK (TPB * ROWS_PER_THREAD)

__global__ __launch_bounds__(TPB, 4)
void dln_kernel(const float* __restrict__ x,
                const float* __restrict__ W1, const float* __restrict__ b1,
                const float* __restrict__ Wd, const float* __restrict__ bd,
                const float* __restrict__ Wo, const float* __restrict__ bo,
                float* __restrict__ out, int n)
{
    // Per j-pair jp (32 of them), 8 u64 = 64B:
    //  [0..3]: k=0..3 -> (W1[2jp][k], W1[2jp+1][k])       (natural j-pair pack)
    //  [4]   : (b1[2jp], b1[2jp+1])
    //  [5..7]: m=0..2 -> 0.495*(V_m[2jp], V_m[2jp+1])
    __shared__ ulonglong2 sw[128];   // sw[jp*4 + 0..3]
    __shared__ float sM[12];         // 0.505*(V_m W1)[k]   (m*4+k)
    __shared__ float sC[3];          // bias_m + 0.505*(V_m . b1)

    float* fS = reinterpret_cast<float*>(sw);
    const int t = threadIdx.x;

    // ---- weight prep (tiny) ----
    {
        int e = t;              // 256 u64 entries, one per thread
        int jp = e >> 3, q = e & 7;
        int j0 = 2 * jp, j1 = j0 + 1;
        float lo, hi;
        if (q < 4) {
            lo = W1[j0 * 4 + q]; hi = W1[j1 * 4 + q];
        } else if (q == 4) {
            lo = b1[j0]; hi = b1[j1];
        } else {
            int m = q - 5;
            const float* Vm = (m < 2) ? (Wd + m * 64) : Wo;
            lo = C_HALF_M * Vm[j0]; hi = C_HALF_M * Vm[j1];
        }
        fS[2 * e] = lo; fS[2 * e + 1] = hi;
    }
    if (t < 12) { // M = 0.505 * (V W1)
        int m = t >> 2, k = t & 3;
        const float* Vm = (m == 0) ? Wd : ((m == 1) ? (Wd + 64) : Wo);
        float s = 0.0f;
        #pragma unroll 8
        for (int j = 0; j < 64; ++j) s = fmaf(Vm[j], W1[j * 4 + k], s);
        sM[t] = C_HALF_P * s;
    }
    if (t >= 12 && t < 15) { // c_m = bias_m + 0.505*(V_m . b1)
        int m = t - 12;
        const float* Vm = (m == 0) ? Wd : ((m == 1) ? (Wd + 64) : Wo);
        float s = 0.0f;
        #pragma unroll 8
        for (int j = 0; j < 64; ++j) s = fmaf(Vm[j], b1[j], s);
        float bias = (m == 0) ? bd[0] : ((m == 1) ? bd[1] : bo[0]);
        sC[m] = bias + C_HALF_P * s;
    }
    __syncthreads();

    const int rowBase = blockIdx.x * ROWS_PER_BLOCK + t;   // coalesced: +i*TPB
    const float4* x4 = reinterpret_cast<const float4*>(x);
    float4* o4 = reinterpret_cast<float4*>(out);
    const u64 ABSM = 0x7fffffff7fffffffULL;

    // ---- load x for 4 rows, keep ONLY dup-packed X (x recovered at epilogue) ----
    u64 X[ROWS_PER_THREAD][4];
    #pragma unroll
    for (int i = 0; i < ROWS_PER_THREAD; ++i) {
        int r = rowBase + i * TPB;
        float4 v = (r < n) ? x4[r] : make_float4(0.f, 0.f, 0.f, 0.f);
        X[i][0] = pk2(v.x, v.x);
        X[i][1] = pk2(v.y, v.y);
        X[i][2] = pk2(v.z, v.z);
        X[i][3] = pk2(v.w, v.w);
    }

    u64 S0[ROWS_PER_THREAD], S1[ROWS_PER_THREAD], S2[ROWS_PER_THREAD];
    #pragma unroll
    for (int i = 0; i < ROWS_PER_THREAD; ++i) { S0[i] = 0ull; S1[i] = 0ull; S2[i] = 0ull; }

    #pragma unroll
    for (int jp = 0; jp < 32; ++jp) {
        ulonglong2 e01 = sw[jp * 4 + 0];  // w k0, k1
        ulonglong2 e23 = sw[jp * 4 + 1];  // w k2, k3
        ulonglong2 e45 = sw[jp * 4 + 2];  // bias, v0
        ulonglong2 e67 = sw[jp * 4 + 3];  // v1, v2

        #pragma unroll
        for (int i = 0; i < ROWS_PER_THREAD; ++i) {
            u64 a = e45.x;                       // (b1[2jp], b1[2jp+1])
            a = ffma2(e01.x, X[i][0], a);
            a = ffma2(e01.y, X[i][1], a);
            a = ffma2(e23.x, X[i][2], a);
            a = ffma2(e23.y, X[i][3], a);
            a &= ABSM;                           // packed |a|
            S0[i] = ffma2(e45.y, a, S0[i]);
            S1[i] = ffma2(e67.x, a, S1[i]);
            S2[i] = ffma2(e67.y, a, S2[i]);
        }
    }

    const float m0 = sM[0], m1 = sM[1], m2 = sM[2],  m3 = sM[3];
    const float m4 = sM[4], m5 = sM[5], m6 = sM[6],  m7 = sM[7];
    const float m8 = sM[8], m9 = sM[9], m10 = sM[10], m11 = sM[11];
    const float c0 = sC[0], c1 = sC[1], c2 = sC[2];

    #pragma unroll
    for (int i = 0; i < ROWS_PER_THREAD; ++i) {
        int r = rowBase + i * TPB;
        if (r >= n) continue;
        float lo_, hi_;
        upk2(S0[i], lo_, hi_); float s0 = lo_ + hi_;
        upk2(S1[i], lo_, hi_); float s1 = lo_ + hi_;
        upk2(S2[i], lo_, hi_); float s2 = lo_ + hi_;

        // recover x_k from the dup-packed halves (free register moves)
        float xk0, xk1, xk2, xk3, junk;
        upk2(X[i][0], xk0, junk);
        upk2(X[i][1], xk1, junk);
        upk2(X[i][2], xk2, junk);
        upk2(X[i][3], xk3, junk);

        float z0 = fmaf(m3,  xk3, fmaf(m2,  xk2, fmaf(m1, xk1, fmaf(m0, xk0, c0)))) + s0;
        float z1 = fmaf(m7,  xk3, fmaf(m6,  xk2, fmaf(m5, xk1, fmaf(m4, xk0, c1)))) + s1;
        float z2 = fmaf(m11, xk3, fmaf(m10, xk2, fmaf(m9, xk1, fmaf(m8, xk0, c2)))) + s2;

        float d0 = softplus_fast(z0);
        float d1 = softplus_fast(z1);
        float l  = z2;
        float4 o;
        o.x = fmaf(d0, d0, 1e-9f);
        o.y = d0 * l;
        o.z = o.y;
        o.w = fmaf(l, l, fmaf(d1, d1, 1e-9f));
        o4[r] = o;
    }
}

extern "C" void kernel_launch(void* const* d_in, const int* in_sizes, int n_in,
                              void* d_out, int out_size)
{
    const float* x  = (const float*)d_in[0];
    const float* W1 = (const float*)d_in[1];
    const float* b1 = (const float*)d_in[2];
    const float* Wd = (const float*)d_in[3];
    const float* bd = (const float*)d_in[4];
    const float* Wo = (const float*)d_in[5];
    const float* bo = (const float*)d_in[6];
    float* out = (float*)d_out;

    int n = in_sizes[0] / 4;                       // rows
    int blocks = (n + ROWS_PER_BLOCK - 1) / ROWS_PER_BLOCK;

    dln_kernel<<<blocks, TPB>>>(x, W1, b1, Wd, bd, Wo, bo, out, n);
}

// round 5
// speedup vs baseline: 1.9919x; 1.1859x over previous
#include <cuda_runtime.h>

typedef unsigned long long u64;

// ---------- f32x2 packed helpers (sm_100+) ----------
static __device__ __forceinline__ u64 pk2(float lo, float hi) {
    u64 r; asm("mov.b64 %0, {%1, %2};" : "=l"(r) : "f"(lo), "f"(hi)); return r;
}
static __device__ __forceinline__ void upk2(u64 v, float& lo, float& hi) {
    asm("mov.b64 {%0, %1}, %2;" : "=f"(lo), "=f"(hi) : "l"(v));
}
static __device__ __forceinline__ u64 ffma2(u64 a, u64 b, u64 c) {
    u64 d; asm("fma.rn.f32x2 %0, %1, %2, %3;" : "=l"(d) : "l"(a), "l"(b), "l"(c)); return d;
}

static __device__ __forceinline__ float softplus_fast(float v) {
    return fmaxf(v, 0.0f) + __logf(1.0f + __expf(-fabsf(v)));
}

#define C_HALF_P 0.505f
#define C_HALF_M 0.495f
#define ROWS_PER_THREAD 4
#define TPB 256
#define ROWS_PER_BLOCK (TPB * ROWS_PER_THREAD)

// Packed per-jp weights: w[jp*8 + q]
//   q=0..3 : (W1[2jp][q], W1[2jp+1][q])
//   q=4    : (b1[2jp],   b1[2jp+1])
//   q=5..7 : 0.495*(V_m[2jp], V_m[2jp+1]), m=q-5
struct ConstsPack {
    u64   w[256];
    float M[12];   // 0.505*(V_m W1)[k]  (m*4+k)
    float C[3];    // bias_m + 0.505*(V_m . b1)
    float pad;
};

__device__ ConstsPack g_scratch;
__constant__ ConstsPack g_c;

// ---- prep kernel: build packed weights into device scratch ----
__global__ void dln_prep(const float* __restrict__ W1, const float* __restrict__ b1,
                         const float* __restrict__ Wd, const float* __restrict__ bd,
                         const float* __restrict__ Wo, const float* __restrict__ bo)
{
    const int t = threadIdx.x;
    {
        int jp = t >> 3, q = t & 7;
        int j0 = 2 * jp, j1 = j0 + 1;
        float lo, hi;
        if (q < 4) {
            lo = W1[j0 * 4 + q]; hi = W1[j1 * 4 + q];
        } else if (q == 4) {
            lo = b1[j0]; hi = b1[j1];
        } else {
            int m = q - 5;
            const float* Vm = (m < 2) ? (Wd + m * 64) : Wo;
            lo = C_HALF_M * Vm[j0]; hi = C_HALF_M * Vm[j1];
        }
        g_scratch.w[t] = pk2(lo, hi);
    }
    if (t < 12) {
        int m = t >> 2, k = t & 3;
        const float* Vm = (m == 0) ? Wd : ((m == 1) ? (Wd + 64) : Wo);
        float s = 0.0f;
        #pragma unroll 8
        for (int j = 0; j < 64; ++j) s = fmaf(Vm[j], W1[j * 4 + k], s);
        g_scratch.M[t] = C_HALF_P * s;
    }
    if (t >= 12 && t < 15) {
        int m = t - 12;
        const float* Vm = (m == 0) ? Wd : ((m == 1) ? (Wd + 64) : Wo);
        float s = 0.0f;
        #pragma unroll 8
        for (int j = 0; j < 64; ++j) s = fmaf(Vm[j], b1[j], s);
        float bias = (m == 0) ? bd[0] : ((m == 1) ? bd[1] : bo[0]);
        g_scratch.C[m] = bias + C_HALF_P * s;
    }
}

// ---- main kernel: weights from __constant__ (uniform-const port / UR path) ----
__global__ __launch_bounds__(TPB, 4)
void dln_kernel(const float* __restrict__ x, float* __restrict__ out, int n)
{
    const int t = threadIdx.x;
    const int rowBase = blockIdx.x * ROWS_PER_BLOCK + t;   // coalesced: +i*TPB
    const float4* x4 = reinterpret_cast<const float4*>(x);
    float4* o4 = reinterpret_cast<float4*>(out);
    const u64 ABSM = 0x7fffffff7fffffffULL;

    u64 X[ROWS_PER_THREAD][4];
    #pragma unroll
    for (int i = 0; i < ROWS_PER_THREAD; ++i) {
        int r = rowBase + i * TPB;
        float4 v = (r < n) ? x4[r] : make_float4(0.f, 0.f, 0.f, 0.f);
        X[i][0] = pk2(v.x, v.x);
        X[i][1] = pk2(v.y, v.y);
        X[i][2] = pk2(v.z, v.z);
        X[i][3] = pk2(v.w, v.w);
    }

    u64 S0[ROWS_PER_THREAD], S1[ROWS_PER_THREAD], S2[ROWS_PER_THREAD];
    #pragma unroll
    for (int i = 0; i < ROWS_PER_THREAD; ++i) { S0[i] = 0ull; S1[i] = 0ull; S2[i] = 0ull; }

    #pragma unroll
    for (int jp = 0; jp < 32; ++jp) {
        const u64 wk0 = g_c.w[jp * 8 + 0];
        const u64 wk1 = g_c.w[jp * 8 + 1];
        const u64 wk2 = g_c.w[jp * 8 + 2];
        const u64 wk3 = g_c.w[jp * 8 + 3];
        const u64 bb  = g_c.w[jp * 8 + 4];
        const u64 v0  = g_c.w[jp * 8 + 5];
        const u64 v1  = g_c.w[jp * 8 + 6];
        const u64 v2  = g_c.w[jp * 8 + 7];

        #pragma unroll
        for (int i = 0; i < ROWS_PER_THREAD; ++i) {
            u64 a = bb;
            a = ffma2(wk0, X[i][0], a);
            a = ffma2(wk1, X[i][1], a);
            a = ffma2(wk2, X[i][2], a);
            a = ffma2(wk3, X[i][3], a);
            a &= ABSM;                           // packed |a|
            S0[i] = ffma2(v0, a, S0[i]);
            S1[i] = ffma2(v1, a, S1[i]);
            S2[i] = ffma2(v2, a, S2[i]);
        }
    }

    const float m0 = g_c.M[0], m1 = g_c.M[1], m2  = g_c.M[2],  m3  = g_c.M[3];
    const float m4 = g_c.M[4], m5 = g_c.M[5], m6  = g_c.M[6],  m7  = g_c.M[7];
    const float m8 = g_c.M[8], m9 = g_c.M[9], m10 = g_c.M[10], m11 = g_c.M[11];
    const float c0 = g_c.C[0], c1 = g_c.C[1], c2  = g_c.C[2];

    #pragma unroll
    for (int i = 0; i < ROWS_PER_THREAD; ++i) {
        int r = rowBase + i * TPB;
        if (r >= n) continue;
        float lo_, hi_;
        upk2(S0[i], lo_, hi_); float s0 = lo_ + hi_;
        upk2(S1[i], lo_, hi_); float s1 = lo_ + hi_;
        upk2(S2[i], lo_, hi_); float s2 = lo_ + hi_;

        float xk0, xk1, xk2, xk3, junk;
        upk2(X[i][0], xk0, junk);
        upk2(X[i][1], xk1, junk);
        upk2(X[i][2], xk2, junk);
        upk2(X[i][3], xk3, junk);

        float z0 = fmaf(m3,  xk3, fmaf(m2,  xk2, fmaf(m1, xk1, fmaf(m0, xk0, c0)))) + s0;
        float z1 = fmaf(m7,  xk3, fmaf(m6,  xk2, fmaf(m5, xk1, fmaf(m4, xk0, c1)))) + s1;
        float z2 = fmaf(m11, xk3, fmaf(m10, xk2, fmaf(m9, xk1, fmaf(m8, xk0, c2)))) + s2;

        float d0 = softplus_fast(z0);
        float d1 = softplus_fast(z1);
        float l  = z2;
        float4 o;
        o.x = fmaf(d0, d0, 1e-9f);
        o.y = d0 * l;
        o.z = o.y;
        o.w = fmaf(l, l, fmaf(d1, d1, 1e-9f));
        o4[r] = o;
    }
}

extern "C" void kernel_launch(void* const* d_in, const int* in_sizes, int n_in,
                              void* d_out, int out_size)
{
    const float* x  = (const float*)d_in[0];
    const float* W1 = (const float*)d_in[1];
    const float* b1 = (const float*)d_in[2];
    const float* Wd = (const float*)d_in[3];
    const float* bd = (const float*)d_in[4];
    const float* Wo = (const float*)d_in[5];
    const float* bo = (const float*)d_in[6];
    float* out = (float*)d_out;

    int n = in_sizes[0] / 4;                       // rows
    int blocks = (n + ROWS_PER_BLOCK - 1) / ROWS_PER_BLOCK;

    // 1) build packed weights in device scratch
    dln_prep<<<1, 256>>>(W1, b1, Wd, bd, Wo, bo);

    // 2) D2D copy scratch -> __constant__ (graph-capturable memcpy node)
    void* src = nullptr;
    cudaGetSymbolAddress(&src, g_scratch);
    cudaMemcpyToSymbolAsync(g_c, src, sizeof(ConstsPack), 0,
                            cudaMemcpyDeviceToDevice, 0);

    // 3) main kernel
    dln_kernel<<<blocks, TPB>>>(x, out, n);
}